// round 5
// baseline (speedup 1.0000x reference)
#include <cuda_runtime.h>
#include <cstdint>

// Problem: B=16384, IN_DIM=1024, D=256, C=100
#define Bsz    16384
#define KDIM   1024
#define DDIM   256
#define CNUM   100
#define CPAD   112

#define BM 64
#define BN 256
#define BK 16
#define NITER (KDIM / BK)    // 64
#define NTHREADS 256
#define NSTG 4

#define ASTRIDE 20           // 16 + 4 pad  (bank = 4*lq + lr, conflict-free)
#define BSTRIDE 264          // 256 + 8 pad (bank = 8*lr + lq, conflict-free)
#define ZSTRIDE 260
#define PSTRIDE 36

#define A_BYTES (BM * ASTRIDE * 4)          // 5120
#define B_BYTES (BK * BSTRIDE * 4)          // 16896
#define STAGE_BYTES (A_BYTES + B_BYTES)     // 22016
#define STAGE_F (STAGE_BYTES / 4)

#define ZS_F   (BM * ZSTRIDE)               // 16640 floats = 66560 B
#define PCH_F  (CPAD * PSTRIDE)             // 4032 floats  = 16128 B
#define DYN_BYTES ((ZS_F + 2 * PCH_F) * 4)  // 98816 B  (> 4*22016 = 88064)

// ---------------------------------------------------------------------------
__device__ __forceinline__ uint32_t smem_u32(const void* p) {
    uint32_t a;
    asm("{ .reg .u64 t; cvta.to.shared.u64 t, %1; cvt.u32.u64 %0, t; }"
        : "=r"(a) : "l"(p));
    return a;
}

#define CP_ASYNC16(dst, src) \
    asm volatile("cp.async.cg.shared.global [%0], [%1], 16;" \
                 :: "r"(dst), "l"(src) : "memory")
#define CP_COMMIT() asm volatile("cp.async.commit_group;" ::: "memory")
#define CP_WAIT2()  asm volatile("cp.async.wait_group 2;" ::: "memory")
#define CP_WAIT1()  asm volatile("cp.async.wait_group 1;" ::: "memory")
#define CP_WAIT0()  asm volatile("cp.async.wait_group 0;" ::: "memory")

// round-to-nearest tf32 (restores accuracy margin; proven perf-free R3 vs R4)
__device__ __forceinline__ uint32_t F2T(float x) {
    uint32_t r;
    asm("cvt.rna.tf32.f32 %0, %1;" : "=r"(r) : "f"(x));
    return r;
}

#define MMA_TF32(d, a, b) \
    asm volatile("mma.sync.aligned.m16n8k8.row.col.f32.tf32.tf32.f32 " \
        "{%0,%1,%2,%3}, {%4,%5,%6,%7}, {%8,%9}, {%0,%1,%2,%3};" \
        : "+f"((d)[0]), "+f"((d)[1]), "+f"((d)[2]), "+f"((d)[3]) \
        : "r"((a)[0]), "r"((a)[1]), "r"((a)[2]), "r"((a)[3]), \
          "r"((b)[0]), "r"((b)[1]))

// ---------------------------------------------------------------------------
// 256 threads / 8 warps, 2 CTAs per SM (grid 256 -> single wave on 148 SMs).
// GEMM1 warp tile: 32 rows x 64 cols  (warp_m = wid&1, warp_n = wid>>1)
// MMA2  warp tile: 16 rows x 56 cols  (warp_m2 = wid>>1, warp_n2 = wid&1)
// ---------------------------------------------------------------------------
__global__ void __launch_bounds__(NTHREADS, 2)
fused_kernel(const float* __restrict__ x,
             const float* __restrict__ W,
             const float* __restrict__ bias,
             const float* __restrict__ P,
             float* __restrict__ out)
{
    extern __shared__ float dyn[];
    __shared__ float s_bias[DDIM];
    __shared__ float srow[BM];
    __shared__ float s_pn[CPAD];

    const int tid  = threadIdx.x;
    const int wid  = tid >> 5;
    const int lane = tid & 31;
    const int mBase = blockIdx.x * BM;

    const int warp_m = wid & 1;    // 0..1 : 32 rows
    const int warp_n = wid >> 1;   // 0..3 : 64 cols

    s_bias[tid] = bias[tid];       // 256 threads == DDIM
    if (tid < BM) srow[tid] = 0.0f;

    const uint32_t dynb = smem_u32(dyn);

    // ---- stage loader: A 256 chunks (1/thr), B 1024 chunks (4/thr) ----
    auto load_stage = [&](int kIter, int slot) {
        const int k0 = kIter * BK;
        const uint32_t aB = dynb + slot * STAGE_BYTES;
        const uint32_t bB = aB + A_BYTES;
        {
            const int row = tid >> 2, seg = tid & 3;
            CP_ASYNC16(aB + row * (ASTRIDE * 4) + seg * 16,
                       x + (size_t)(mBase + row) * KDIM + k0 + seg * 4);
        }
#pragma unroll
        for (int i = 0; i < 4; i++) {
            const int c = tid + (i << 8);
            const int k = c >> 6, seg = c & 63;
            CP_ASYNC16(bB + k * (BSTRIDE * 4) + seg * 16,
                       W + (size_t)(k0 + k) * DDIM + seg * 4);
        }
    };

    load_stage(0, 0); CP_COMMIT();
    load_stage(1, 1); CP_COMMIT();
    load_stage(2, 2); CP_COMMIT();

    float acc[2][8][4];
#pragma unroll
    for (int i = 0; i < 2; i++)
#pragma unroll
        for (int j = 0; j < 8; j++)
#pragma unroll
            for (int r = 0; r < 4; r++) acc[i][j][r] = 0.0f;

    const int lq = lane >> 2;
    const int lr = lane & 3;

    // ---- GEMM1 mainloop (single barrier per iteration) ----
    for (int it = 0; it < NITER; ++it) {
        if (it >= NITER - 2) { CP_WAIT0(); } else { CP_WAIT2(); }
        __syncthreads();

        // issue next stage right after the barrier (overlaps with compute)
        if (it + 3 < NITER) { load_stage(it + 3, (it + 3) & 3); CP_COMMIT(); }

        const float* As = dyn + (it & 3) * STAGE_F;
        const float* Bs = As + A_BYTES / 4;
        const float* aP = As + (warp_m * 32 + lq) * ASTRIDE + lr;
        const float* bP = Bs + lr * BSTRIDE + warp_n * 64 + lq;

#pragma unroll
        for (int kk = 0; kk < 2; kk++) {
            uint32_t au[2][4], bu[8][2];
#pragma unroll
            for (int mi = 0; mi < 2; mi++) {
                const float* p = aP + mi * 16 * ASTRIDE + kk * 8;
                au[mi][0] = F2T(p[0]);
                au[mi][1] = F2T(p[8 * ASTRIDE]);
                au[mi][2] = F2T(p[4]);
                au[mi][3] = F2T(p[8 * ASTRIDE + 4]);
            }
#pragma unroll
            for (int nj = 0; nj < 8; nj++) {
                const float* p = bP + kk * 8 * BSTRIDE + nj * 8;
                bu[nj][0] = F2T(p[0]);
                bu[nj][1] = F2T(p[4 * BSTRIDE]);
            }
#pragma unroll
            for (int mi = 0; mi < 2; mi++)
#pragma unroll
                for (int nj = 0; nj < 8; nj++)
                    MMA_TF32(acc[mi][nj], au[mi], bu[nj]);
        }
    }
    __syncthreads();   // protect smem reuse (stages -> Zs/P buffers)

    // ======================= epilogue A ====================================
    float* Zs  = dyn;                      // [BM][ZSTRIDE]
    float* Pb0 = dyn + ZS_F;
    const uint32_t pb0u = dynb + ZS_F * 4;

    // zero pad rows (classes 100..111) of both P chunk buffers
    for (int i = tid; i < 2 * 12 * PSTRIDE; i += NTHREADS) {
        const int buf = i / (12 * PSTRIDE);
        const int j   = i % (12 * PSTRIDE);
        Pb0[buf * PCH_F + (CNUM + j / PSTRIDE) * PSTRIDE + (j % PSTRIDE)] = 0.0f;
    }

    auto load_pchunk = [&](int kc, int buf) {
        const uint32_t base = pb0u + buf * (PCH_F * 4);
#pragma unroll
        for (int i = 0; i < 4; i++) {
            const int c = tid + (i << 8);
            if (c < CNUM * 8) {
                const int row = c >> 3, seg = c & 7;
                CP_ASYNC16(base + row * (PSTRIDE * 4) + seg * 16,
                           P + (size_t)row * DDIM + kc * 32 + seg * 4);
            }
        }
    };
    load_pchunk(0, 0); CP_COMMIT();

    // bias + rowsq + Z -> smem
    {
        float rsum[2][2];
#pragma unroll
        for (int mi = 0; mi < 2; mi++) { rsum[mi][0] = 0.f; rsum[mi][1] = 0.f; }

#pragma unroll
        for (int mi = 0; mi < 2; mi++) {
            const int rowA = warp_m * 32 + mi * 16 + lq;
#pragma unroll
            for (int nj = 0; nj < 8; nj++) {
                const int n0 = warp_n * 64 + nj * 8 + 2 * lr;
                float v0 = acc[mi][nj][0] + s_bias[n0];
                float v1 = acc[mi][nj][1] + s_bias[n0 + 1];
                float v2 = acc[mi][nj][2] + s_bias[n0];
                float v3 = acc[mi][nj][3] + s_bias[n0 + 1];
                rsum[mi][0] += v0 * v0 + v1 * v1;
                rsum[mi][1] += v2 * v2 + v3 * v3;
                *reinterpret_cast<float2*>(&Zs[rowA * ZSTRIDE + n0]) =
                    make_float2(v0, v1);
                *reinterpret_cast<float2*>(&Zs[(rowA + 8) * ZSTRIDE + n0]) =
                    make_float2(v2, v3);
            }
        }
#pragma unroll
        for (int mi = 0; mi < 2; mi++) {
#pragma unroll
            for (int h = 0; h < 2; h++) {
                float s = rsum[mi][h];
                s += __shfl_xor_sync(0xffffffffu, s, 1);
                s += __shfl_xor_sync(0xffffffffu, s, 2);
                if (lr == 0)
                    atomicAdd(&srow[warp_m * 32 + mi * 16 + lq + 8 * h], s);
            }
        }
    }

    // |P_c|^2 : warp w covers classes w*14 .. w*14+13  (8*14 = 112 = CPAD)
#pragma unroll
    for (int i = 0; i < 14; i++) {
        const int c = wid * 14 + i;
        float s = 0.0f;
        if (c < CNUM) {
#pragma unroll
            for (int e = 0; e < 8; e++) {
                float t = P[(size_t)c * DDIM + e * 32 + lane];
                s += t * t;
            }
        }
        s += __shfl_xor_sync(0xffffffffu, s, 16);
        s += __shfl_xor_sync(0xffffffffu, s, 8);
        s += __shfl_xor_sync(0xffffffffu, s, 4);
        s += __shfl_xor_sync(0xffffffffu, s, 2);
        s += __shfl_xor_sync(0xffffffffu, s, 1);
        if (lane == 0) s_pn[c] = s;
    }

    // ======================= phase 2: MMA2 =================================
    const int warp_m2 = wid >> 1;   // 0..3 : 16 rows
    const int warp_n2 = wid & 1;    // 0..1 : 56 cols

    float acc2[7][4];
#pragma unroll
    for (int j = 0; j < 7; j++)
#pragma unroll
        for (int r = 0; r < 4; r++) acc2[j][r] = 0.0f;

    const int zrow = warp_m2 * 16 + lq;

    for (int kc = 0; kc < 8; kc++) {
        if (kc + 1 < 8) { load_pchunk(kc + 1, (kc + 1) & 1); CP_COMMIT(); }
        if (kc + 1 < 8) { CP_WAIT1(); } else { CP_WAIT0(); }
        __syncthreads();

        const float* Ps = Pb0 + (kc & 1) * PCH_F;
        const float* pP = Ps + (warp_n2 * 56 + lq) * PSTRIDE + lr;
        const float* zP = Zs + zrow * ZSTRIDE + kc * 32 + lr;

#pragma unroll
        for (int kk = 0; kk < 4; kk++) {
            uint32_t au[4], bu[7][2];
            const float* zp = zP + kk * 8;
            au[0] = F2T(zp[0]);
            au[1] = F2T(zp[8 * ZSTRIDE]);
            au[2] = F2T(zp[4]);
            au[3] = F2T(zp[8 * ZSTRIDE + 4]);
#pragma unroll
            for (int nj = 0; nj < 7; nj++) {
                const float* p = pP + nj * 8 * PSTRIDE + kk * 8;
                bu[nj][0] = F2T(p[0]);
                bu[nj][1] = F2T(p[4]);
            }
#pragma unroll
            for (int nj = 0; nj < 7; nj++)
                MMA_TF32(acc2[nj], au, bu[nj]);
        }
        __syncthreads();
    }

    // ======================= epilogue B ====================================
    const float inv = 1.0f / (float)DDIM;
    const int rowA = warp_m2 * 16 + lq;
    const int rowB = rowA + 8;
    const float rsA = srow[rowA];
    const float rsB = srow[rowB];
#pragma unroll
    for (int nj = 0; nj < 7; nj++) {
        const int c0 = warp_n2 * 56 + nj * 8 + 2 * lr;
        const float pn0 = s_pn[c0];
        const float pn1 = s_pn[c0 + 1];
        if (c0 < CNUM)
            out[(size_t)(mBase + rowA) * CNUM + c0] =
                (2.0f * acc2[nj][0] - rsA - pn0) * inv;
        if (c0 + 1 < CNUM)
            out[(size_t)(mBase + rowA) * CNUM + c0 + 1] =
                (2.0f * acc2[nj][1] - rsA - pn1) * inv;
        if (c0 < CNUM)
            out[(size_t)(mBase + rowB) * CNUM + c0] =
                (2.0f * acc2[nj][2] - rsB - pn0) * inv;
        if (c0 + 1 < CNUM)
            out[(size_t)(mBase + rowB) * CNUM + c0 + 1] =
                (2.0f * acc2[nj][3] - rsB - pn1) * inv;
    }
}

// ---------------------------------------------------------------------------
extern "C" void kernel_launch(void* const* d_in, const int* in_sizes, int n_in,
                              void* d_out, int out_size)
{
    const float* x  = (const float*)d_in[0];
    const float* W  = (const float*)d_in[1];
    const float* b  = (const float*)d_in[2];
    const float* P  = (const float*)d_in[3];
    float* out = (float*)d_out;

    cudaFuncSetAttribute(fused_kernel,
                         cudaFuncAttributeMaxDynamicSharedMemorySize, DYN_BYTES);

    fused_kernel<<<Bsz / BM, NTHREADS, DYN_BYTES>>>(x, W, b, P, out);
}

// round 6
// speedup vs baseline: 1.5067x; 1.5067x over previous
#include <cuda_runtime.h>
#include <cuda_fp16.h>
#include <cstdint>

// Problem: B=16384, IN_DIM=1024, D=256, C=100
#define Bsz    16384
#define KDIM   1024
#define DDIM   256
#define CNUM   100
#define CPAD   112

#define BM 128
#define BK 64
#define NITER (KDIM / BK)     // 16
#define NT 512

// fp16-element strides; all satisfy (stride/2) % 32 == 4 -> conflict-free
// b32 fragment loads (lane word addr = row*(stride/2) + lr).
#define AST 72      // A tile row: 64 data + 8 pad
#define BST 72      // B tile row (n-major [n][k])
#define ZST 264     // Z smem row: 256 data + 8 pad
#define PST 72      // P chunk row: 64 data + 8 pad

#define A_BYTES (BM * AST * 2)          // 18432
#define B_BYTES (256 * BST * 2)         // 36864
#define STAGE_BYTES (A_BYTES + B_BYTES) // 55296
#define DYN_BYTES (3 * STAGE_BYTES)     // 165888

#define ZS_BYTES (BM * ZST * 2)         // 67584
#define PCH_BYTES (CPAD * PST * 2)      // 16128

// Pre-converted fp16 operands (device globals: allocation-free)
__device__ __half g_xh[(size_t)Bsz * KDIM];   // 32 MB
__device__ __half g_wt[(size_t)DDIM * KDIM];  // W^T, [n][k]
__device__ __half g_ph[CPAD * DDIM];          // P padded, [c][k]
__device__ float  g_pn[CPAD];                 // |P_c|^2

// ---------------------------------------------------------------------------
__device__ __forceinline__ uint32_t smem_u32(const void* p) {
    uint32_t a;
    asm("{ .reg .u64 t; cvta.to.shared.u64 t, %1; cvt.u32.u64 %0, t; }"
        : "=r"(a) : "l"(p));
    return a;
}

#define CP_ASYNC16(dst, src) \
    asm volatile("cp.async.cg.shared.global [%0], [%1], 16;" \
                 :: "r"(dst), "l"(src) : "memory")
#define CP_COMMIT() asm volatile("cp.async.commit_group;" ::: "memory")
#define CP_WAIT1()  asm volatile("cp.async.wait_group 1;" ::: "memory")
#define CP_WAIT0()  asm volatile("cp.async.wait_group 0;" ::: "memory")

#define MMA_F16(d, a, b) \
    asm volatile("mma.sync.aligned.m16n8k16.row.col.f32.f16.f16.f32 " \
        "{%0,%1,%2,%3}, {%4,%5,%6,%7}, {%8,%9}, {%0,%1,%2,%3};" \
        : "+f"((d)[0]), "+f"((d)[1]), "+f"((d)[2]), "+f"((d)[3]) \
        : "r"((a)[0]), "r"((a)[1]), "r"((a)[2]), "r"((a)[3]), \
          "r"((b)[0]), "r"((b)[1]))

// ---------------------------------------------------------------------------
// Pre-pass 1: x fp32 -> g_xh fp16.  16.78M elems, 8 per thread.
// ---------------------------------------------------------------------------
__global__ void __launch_bounds__(256)
conv_x_kernel(const float* __restrict__ x) {
    const size_t i = ((size_t)blockIdx.x * 256 + threadIdx.x) * 8;
    float4 v0 = *reinterpret_cast<const float4*>(x + i);
    float4 v1 = *reinterpret_cast<const float4*>(x + i + 4);
    __half2 h[4];
    h[0] = __floats2half2_rn(v0.x, v0.y);
    h[1] = __floats2half2_rn(v0.z, v0.w);
    h[2] = __floats2half2_rn(v1.x, v1.y);
    h[3] = __floats2half2_rn(v1.z, v1.w);
    *reinterpret_cast<uint4*>(&g_xh[i]) = *reinterpret_cast<uint4*>(h);
}

// ---------------------------------------------------------------------------
// Pre-pass 2: W [1024,256] fp32 -> g_wt [256,1024] fp16 (transpose+convert)
// ---------------------------------------------------------------------------
__global__ void conv_wt_kernel(const float* __restrict__ W) {
    __shared__ float t[32][33];
    const int bx = blockIdx.x * 32;   // n
    const int by = blockIdx.y * 32;   // k
    const int tx = threadIdx.x, ty = threadIdx.y;
#pragma unroll
    for (int j = 0; j < 32; j += 8)
        t[ty + j][tx] = W[(size_t)(by + ty + j) * DDIM + bx + tx];
    __syncthreads();
#pragma unroll
    for (int j = 0; j < 32; j += 8)
        g_wt[(size_t)(bx + ty + j) * KDIM + by + tx] = __float2half_rn(t[tx][ty + j]);
}

// ---------------------------------------------------------------------------
// Pre-pass 3: P -> g_ph fp16 ([c][k], rows >=100 zero) + g_pn = |P_c|^2
// grid = CPAD blocks x 64 threads.
// ---------------------------------------------------------------------------
__global__ void conv_p_kernel(const float* __restrict__ P) {
    __shared__ float wsum[2];
    const int c = blockIdx.x;
    const int tid = threadIdx.x;
    float s = 0.0f;
    __half2 h0 = __floats2half2_rn(0.f, 0.f), h1 = h0;
    if (c < CNUM) {
        float4 v = reinterpret_cast<const float4*>(P + (size_t)c * DDIM)[tid];
        h0 = __floats2half2_rn(v.x, v.y);
        h1 = __floats2half2_rn(v.z, v.w);
        s = v.x * v.x + v.y * v.y + v.z * v.z + v.w * v.w;
    }
    reinterpret_cast<__half2*>(g_ph + c * DDIM)[tid * 2]     = h0;
    reinterpret_cast<__half2*>(g_ph + c * DDIM)[tid * 2 + 1] = h1;
#pragma unroll
    for (int o = 16; o > 0; o >>= 1) s += __shfl_xor_sync(0xffffffffu, s, o);
    if ((tid & 31) == 0) wsum[tid >> 5] = s;
    __syncthreads();
    if (tid == 0) g_pn[c] = wsum[0] + wsum[1];
}

// ---------------------------------------------------------------------------
// Fused kernel: 512 thr / 16 warps, grid 128 (one wave).
// GEMM1 (fp16 m16n8k16): Z[128,256] = x@W ; warp tile 64m x 32n.
// Epilogue A: +bias, rowsq, Z -> smem fp16.
// MMA2: dot[128,112] = Z @ P^T ; warp tile 16m x 56n.
// Epilogue B: out = (2*dot - |z|^2 - |p|^2)/256.
// ---------------------------------------------------------------------------
__global__ void __launch_bounds__(NT, 1)
fused_kernel(const float* __restrict__ bias,
             float* __restrict__ out)
{
    extern __shared__ __align__(16) unsigned char dyn[];
    __shared__ float s_bias[DDIM];
    __shared__ float srow[BM];
    __shared__ float s_pn[CPAD];

    const int tid  = threadIdx.x;
    const int wid  = tid >> 5;
    const int lane = tid & 31;
    const int lq = lane >> 2;      // 0..7
    const int lr = lane & 3;       // 0..3
    const int mBase = blockIdx.x * BM;

    const int warp_m = wid & 1;    // 0..1 : 64 rows
    const int warp_n = wid >> 1;   // 0..7 : 32 cols

    if (tid < DDIM) s_bias[tid] = bias[tid];
    if (tid < BM)   srow[tid] = 0.0f;
    if (tid < CPAD) s_pn[tid] = g_pn[tid];

    const uint32_t dynb = smem_u32(dyn);

    // ---- stage loader: A 1024 chunks (2/thr), B 2048 chunks (4/thr) ----
    auto load_stage = [&](int kIter, int slot) {
        const int k0 = kIter * BK;
        const uint32_t aB = dynb + slot * STAGE_BYTES;
        const uint32_t bB = aB + A_BYTES;
#pragma unroll
        for (int i = 0; i < 2; i++) {
            const int c = tid + (i << 9);
            const int row = c >> 3, seg = c & 7;
            CP_ASYNC16(aB + row * (AST * 2) + seg * 16,
                       g_xh + (size_t)(mBase + row) * KDIM + k0 + seg * 8);
        }
#pragma unroll
        for (int i = 0; i < 4; i++) {
            const int c = tid + (i << 9);
            const int row = c >> 3, seg = c & 7;
            CP_ASYNC16(bB + row * (BST * 2) + seg * 16,
                       g_wt + (size_t)row * KDIM + k0 + seg * 8);
        }
    };

    load_stage(0, 0); CP_COMMIT();
    load_stage(1, 1); CP_COMMIT();

    float acc[4][4][4];
#pragma unroll
    for (int i = 0; i < 4; i++)
#pragma unroll
        for (int j = 0; j < 4; j++)
#pragma unroll
            for (int r = 0; r < 4; r++) acc[i][j][r] = 0.0f;

    // ---- GEMM1 mainloop ----
    for (int it = 0; it < NITER; ++it) {
        if (it == NITER - 1) { CP_WAIT0(); } else { CP_WAIT1(); }
        __syncthreads();
        if (it + 2 < NITER) { load_stage(it + 2, (it + 2) % 3); CP_COMMIT(); }

        const uint32_t* As = reinterpret_cast<const uint32_t*>(
            dyn + (it % 3) * STAGE_BYTES);
        const uint32_t* Bs = As + A_BYTES / 4;
        const uint32_t* aP = As + (warp_m * 64 + lq) * (AST / 2) + lr;
        const uint32_t* bP = Bs + (warp_n * 32 + lq) * (BST / 2) + lr;

#pragma unroll
        for (int kk = 0; kk < 4; kk++) {     // 4 x k16
            uint32_t au[4][4], bu[4][2];
#pragma unroll
            for (int mi = 0; mi < 4; mi++) {
                const uint32_t* p = aP + mi * 16 * (AST / 2) + kk * 8;
                au[mi][0] = p[0];
                au[mi][1] = p[8 * (AST / 2)];
                au[mi][2] = p[4];
                au[mi][3] = p[8 * (AST / 2) + 4];
            }
#pragma unroll
            for (int nj = 0; nj < 4; nj++) {
                const uint32_t* p = bP + nj * 8 * (BST / 2) + kk * 8;
                bu[nj][0] = p[0];
                bu[nj][1] = p[4];
            }
#pragma unroll
            for (int mi = 0; mi < 4; mi++)
#pragma unroll
                for (int nj = 0; nj < 4; nj++)
                    MMA_F16(acc[mi][nj], au[mi], bu[nj]);
        }
    }
    __syncthreads();   // stage buffers dead; smem region reused below

    // ======================= epilogue A ====================================
    __half2* Zs2 = reinterpret_cast<__half2*>(dyn);            // [BM][ZST/2]
    const uint32_t pbu = dynb + ZS_BYTES;                      // P chunk bufs

    auto load_pchunk = [&](int kc, int buf) {
        const uint32_t base = pbu + buf * PCH_BYTES;
#pragma unroll
        for (int i = 0; i < 2; i++) {
            const int c = tid + (i << 9);
            if (c < CPAD * 8) {
                const int row = c >> 3, seg = c & 7;
                CP_ASYNC16(base + row * (PST * 2) + seg * 16,
                           g_ph + row * DDIM + kc * 64 + seg * 8);
            }
        }
    };
    load_pchunk(0, 0); CP_COMMIT();

    {
        float rsum[4][2];
#pragma unroll
        for (int mi = 0; mi < 4; mi++) { rsum[mi][0] = 0.f; rsum[mi][1] = 0.f; }

#pragma unroll
        for (int mi = 0; mi < 4; mi++) {
            const int rowA = warp_m * 64 + mi * 16 + lq;
#pragma unroll
            for (int nj = 0; nj < 4; nj++) {
                const int n0 = warp_n * 32 + nj * 8 + 2 * lr;
                float v0 = acc[mi][nj][0] + s_bias[n0];
                float v1 = acc[mi][nj][1] + s_bias[n0 + 1];
                float v2 = acc[mi][nj][2] + s_bias[n0];
                float v3 = acc[mi][nj][3] + s_bias[n0 + 1];
                rsum[mi][0] += v0 * v0 + v1 * v1;
                rsum[mi][1] += v2 * v2 + v3 * v3;
                Zs2[rowA * (ZST / 2) + (n0 >> 1)] = __floats2half2_rn(v0, v1);
                Zs2[(rowA + 8) * (ZST / 2) + (n0 >> 1)] = __floats2half2_rn(v2, v3);
            }
        }
#pragma unroll
        for (int mi = 0; mi < 4; mi++) {
#pragma unroll
            for (int h = 0; h < 2; h++) {
                float s = rsum[mi][h];
                s += __shfl_xor_sync(0xffffffffu, s, 1);
                s += __shfl_xor_sync(0xffffffffu, s, 2);
                if (lr == 0)
                    atomicAdd(&srow[warp_m * 64 + mi * 16 + lq + 8 * h], s);
            }
        }
    }

    // ======================= phase 2: MMA2 =================================
    const int warp_m2 = wid >> 1;   // 0..7 : 16 rows
    const int warp_n2 = wid & 1;    // 0..1 : 56 cols

    float acc2[7][4];
#pragma unroll
    for (int j = 0; j < 7; j++)
#pragma unroll
        for (int r = 0; r < 4; r++) acc2[j][r] = 0.0f;

    const uint32_t* Zs32 = reinterpret_cast<const uint32_t*>(dyn);
    const uint32_t* zP = Zs32 + (warp_m2 * 16 + lq) * (ZST / 2) + lr;

    for (int kc = 0; kc < 4; kc++) {          // 4 chunks of k64
        if (kc + 1 < 4) { load_pchunk(kc + 1, (kc + 1) & 1); CP_COMMIT(); }
        if (kc + 1 < 4) { CP_WAIT1(); } else { CP_WAIT0(); }
        __syncthreads();

        const uint32_t* Ps = reinterpret_cast<const uint32_t*>(
            dyn + ZS_BYTES + (kc & 1) * PCH_BYTES);
        const uint32_t* pP = Ps + (warp_n2 * 56 + lq) * (PST / 2) + lr;

#pragma unroll
        for (int kk = 0; kk < 4; kk++) {      // k16 within chunk
            uint32_t au[4], bu[7][2];
            const uint32_t* zp = zP + kc * 32 + kk * 8;
            au[0] = zp[0];
            au[1] = zp[8 * (ZST / 2)];
            au[2] = zp[4];
            au[3] = zp[8 * (ZST / 2) + 4];
#pragma unroll
            for (int nj = 0; nj < 7; nj++) {
                const uint32_t* p = pP + nj * 8 * (PST / 2) + kk * 8;
                bu[nj][0] = p[0];
                bu[nj][1] = p[4];
            }
#pragma unroll
            for (int nj = 0; nj < 7; nj++)
                MMA_F16(acc2[nj], au, bu[nj]);
        }
        __syncthreads();
    }

    // ======================= epilogue B ====================================
    const float inv = 1.0f / (float)DDIM;
    const int rowA = warp_m2 * 16 + lq;
    const int rowB = rowA + 8;
    const float rsA = srow[rowA];
    const float rsB = srow[rowB];
#pragma unroll
    for (int nj = 0; nj < 7; nj++) {
        const int c0 = warp_n2 * 56 + nj * 8 + 2 * lr;
        const float pn0 = s_pn[c0];
        const float pn1 = s_pn[c0 + 1];
        if (c0 < CNUM)
            out[(size_t)(mBase + rowA) * CNUM + c0] =
                (2.0f * acc2[nj][0] - rsA - pn0) * inv;
        if (c0 + 1 < CNUM)
            out[(size_t)(mBase + rowA) * CNUM + c0 + 1] =
                (2.0f * acc2[nj][1] - rsA - pn1) * inv;
        if (c0 < CNUM)
            out[(size_t)(mBase + rowB) * CNUM + c0] =
                (2.0f * acc2[nj][2] - rsB - pn0) * inv;
        if (c0 + 1 < CNUM)
            out[(size_t)(mBase + rowB) * CNUM + c0 + 1] =
                (2.0f * acc2[nj][3] - rsB - pn1) * inv;
    }
}

// ---------------------------------------------------------------------------
extern "C" void kernel_launch(void* const* d_in, const int* in_sizes, int n_in,
                              void* d_out, int out_size)
{
    const float* x  = (const float*)d_in[0];
    const float* W  = (const float*)d_in[1];
    const float* b  = (const float*)d_in[2];
    const float* P  = (const float*)d_in[3];
    float* out = (float*)d_out;

    cudaFuncSetAttribute(fused_kernel,
                         cudaFuncAttributeMaxDynamicSharedMemorySize, DYN_BYTES);

    conv_x_kernel<<<(Bsz * KDIM) / (256 * 8), 256>>>(x);
    conv_wt_kernel<<<dim3(DDIM / 32, KDIM / 32), dim3(32, 8)>>>(W);
    conv_p_kernel<<<CPAD, 64>>>(P);
    fused_kernel<<<Bsz / BM, NT, DYN_BYTES>>>(b, out);
}

// round 7
// speedup vs baseline: 1.5075x; 1.0005x over previous
#include <cuda_runtime.h>
#include <cuda_fp16.h>
#include <cstdint>

// Problem: B=16384, IN_DIM=1024, D=256, C=100
#define Bsz    16384
#define KDIM   1024
#define DDIM   256
#define CNUM   100
#define CPAD   112

#define BM 64
#define BK 64
#define NITER (KDIM / BK)     // 16
#define NT 256

// fp16-element strides; (stride/2) % 32 == 4 -> conflict-free b32 frag LDS
#define AST 72
#define BST 72
#define ZST 264
#define PST 72

#define A_BYTES (BM * AST * 2)          // 9216
#define B_BYTES (256 * BST * 2)         // 36864
#define STAGE_BYTES (A_BYTES + B_BYTES) // 46080
#define DYN_BYTES (2 * STAGE_BYTES)     // 92160

#define ZS_BYTES (BM * ZST * 2)         // 33792
#define PCH_BYTES (CPAD * PST * 2)      // 16128

// Pre-converted fp16 operands (device globals: allocation-free)
__device__ __half g_xh[(size_t)Bsz * KDIM];   // 32 MB
__device__ __half g_wt[(size_t)DDIM * KDIM];  // W^T, [n][k]
__device__ __half g_ph[CPAD * DDIM];          // P padded, [c][k]
__device__ float  g_pn[CPAD];                 // |P_c|^2

// ---------------------------------------------------------------------------
__device__ __forceinline__ uint32_t smem_u32(const void* p) {
    uint32_t a;
    asm("{ .reg .u64 t; cvta.to.shared.u64 t, %1; cvt.u32.u64 %0, t; }"
        : "=r"(a) : "l"(p));
    return a;
}

#define CP_ASYNC16(dst, src) \
    asm volatile("cp.async.cg.shared.global [%0], [%1], 16;" \
                 :: "r"(dst), "l"(src) : "memory")
#define CP_COMMIT() asm volatile("cp.async.commit_group;" ::: "memory")
#define CP_WAIT1()  asm volatile("cp.async.wait_group 1;" ::: "memory")
#define CP_WAIT0()  asm volatile("cp.async.wait_group 0;" ::: "memory")

#define MMA_F16(d, a, b) \
    asm volatile("mma.sync.aligned.m16n8k16.row.col.f32.f16.f16.f32 " \
        "{%0,%1,%2,%3}, {%4,%5,%6,%7}, {%8,%9}, {%0,%1,%2,%3};" \
        : "+f"((d)[0]), "+f"((d)[1]), "+f"((d)[2]), "+f"((d)[3]) \
        : "r"((a)[0]), "r"((a)[1]), "r"((a)[2]), "r"((a)[3]), \
          "r"((b)[0]), "r"((b)[1]))

// ---------------------------------------------------------------------------
// Combined pre-pass (one launch):
//   blocks [0, 8192)        : x fp32 -> g_xh fp16 (8 elems/thread)
//   blocks [8192, 8448)     : W [1024,256] -> g_wt [256,1024] fp16 transpose
//   blocks [8448, 8462)     : P -> g_ph fp16 padded + g_pn = |P_c|^2
// ---------------------------------------------------------------------------
#define XBLKS 8192
#define WBLKS 256
#define PBLKS 14
#define PREP_GRID (XBLKS + WBLKS + PBLKS)

__global__ void __launch_bounds__(256)
prep_kernel(const float* __restrict__ x,
            const float* __restrict__ W,
            const float* __restrict__ P)
{
    const int b   = blockIdx.x;
    const int tid = threadIdx.x;

    if (b < XBLKS) {
        const size_t i = ((size_t)b * 256 + tid) * 8;
        float4 v0 = *reinterpret_cast<const float4*>(x + i);
        float4 v1 = *reinterpret_cast<const float4*>(x + i + 4);
        __half2 h[4];
        h[0] = __floats2half2_rn(v0.x, v0.y);
        h[1] = __floats2half2_rn(v0.z, v0.w);
        h[2] = __floats2half2_rn(v1.x, v1.y);
        h[3] = __floats2half2_rn(v1.z, v1.w);
        *reinterpret_cast<uint4*>(&g_xh[i]) = *reinterpret_cast<uint4*>(h);
    } else if (b < XBLKS + WBLKS) {
        __shared__ float t[32][33];
        const int l  = b - XBLKS;
        const int bx = (l & 7) * 32;    // n
        const int by = (l >> 3) * 32;   // k
        const int tx = tid & 31, ty = tid >> 5;   // ty 0..7
#pragma unroll
        for (int j = 0; j < 32; j += 8)
            t[ty + j][tx] = W[(size_t)(by + ty + j) * DDIM + bx + tx];
        __syncthreads();
#pragma unroll
        for (int j = 0; j < 32; j += 8)
            g_wt[(size_t)(bx + ty + j) * KDIM + by + tx] =
                __float2half_rn(t[tx][ty + j]);
    } else {
        // 8 warps per block, 1 class per warp
        const int c    = (b - XBLKS - WBLKS) * 8 + (tid >> 5);
        const int lane = tid & 31;
        float4 v0 = make_float4(0.f, 0.f, 0.f, 0.f), v1 = v0;
        if (c < CNUM) {
            const float4* p4 = reinterpret_cast<const float4*>(P + (size_t)c * DDIM);
            v0 = p4[lane];
            v1 = p4[lane + 32];
        }
        __half2 h0[2] = { __floats2half2_rn(v0.x, v0.y), __floats2half2_rn(v0.z, v0.w) };
        __half2 h1[2] = { __floats2half2_rn(v1.x, v1.y), __floats2half2_rn(v1.z, v1.w) };
        *reinterpret_cast<uint2*>(&g_ph[c * DDIM + lane * 4])       = *reinterpret_cast<uint2*>(h0);
        *reinterpret_cast<uint2*>(&g_ph[c * DDIM + 128 + lane * 4]) = *reinterpret_cast<uint2*>(h1);
        float s = v0.x * v0.x + v0.y * v0.y + v0.z * v0.z + v0.w * v0.w
                + v1.x * v1.x + v1.y * v1.y + v1.z * v1.z + v1.w * v1.w;
#pragma unroll
        for (int o = 16; o > 0; o >>= 1) s += __shfl_xor_sync(0xffffffffu, s, o);
        if (lane == 0) g_pn[c] = s;
    }
}

// ---------------------------------------------------------------------------
// Fused kernel: 256 thr / 8 warps, grid 256 -> 2 CTAs per SM (one wave).
// GEMM1 (fp16 m16n8k16): Z[64,256] = x@W ; warp tile 32m x 64n.
// Epilogue A: +bias, rowsq, Z -> smem fp16.
// MMA2: dot[64,112] = Z @ P^T ; warp tile 16m x 56n.
// Epilogue B: out = (2*dot - |z|^2 - |p|^2)/256.
// ---------------------------------------------------------------------------
__global__ void __launch_bounds__(NT, 2)
fused_kernel(const float* __restrict__ bias,
             float* __restrict__ out)
{
    extern __shared__ __align__(16) unsigned char dyn[];
    __shared__ float s_bias[DDIM];
    __shared__ float srow[BM];
    __shared__ float s_pn[CPAD];

    const int tid  = threadIdx.x;
    const int wid  = tid >> 5;
    const int lane = tid & 31;
    const int lq = lane >> 2;      // 0..7
    const int lr = lane & 3;       // 0..3
    const int mBase = blockIdx.x * BM;

    const int warp_m = wid & 1;    // 0..1 : 32 rows
    const int warp_n = wid >> 1;   // 0..3 : 64 cols

    s_bias[tid] = bias[tid];       // 256 == DDIM
    if (tid < BM)   srow[tid] = 0.0f;
    if (tid < CPAD) s_pn[tid] = g_pn[tid];

    const uint32_t dynb = smem_u32(dyn);

    // ---- stage loader: A 512 chunks (2/thr), B 2048 chunks (8/thr) ----
    auto load_stage = [&](int kIter, int slot) {
        const int k0 = kIter * BK;
        const uint32_t aB = dynb + slot * STAGE_BYTES;
        const uint32_t bB = aB + A_BYTES;
#pragma unroll
        for (int i = 0; i < 2; i++) {
            const int c = tid + (i << 8);
            const int row = c >> 3, seg = c & 7;
            CP_ASYNC16(aB + row * (AST * 2) + seg * 16,
                       g_xh + (size_t)(mBase + row) * KDIM + k0 + seg * 8);
        }
#pragma unroll
        for (int i = 0; i < 8; i++) {
            const int c = tid + (i << 8);
            const int row = c >> 3, seg = c & 7;
            CP_ASYNC16(bB + row * (BST * 2) + seg * 16,
                       g_wt + (size_t)row * KDIM + k0 + seg * 8);
        }
    };

    load_stage(0, 0); CP_COMMIT();
    load_stage(1, 1); CP_COMMIT();

    float acc[2][8][4];
#pragma unroll
    for (int i = 0; i < 2; i++)
#pragma unroll
        for (int j = 0; j < 8; j++)
#pragma unroll
            for (int r = 0; r < 4; r++) acc[i][j][r] = 0.0f;

    // ---- GEMM1 mainloop (2-stage) ----
    for (int it = 0; it < NITER; ++it) {
        if (it >= NITER - 1) { CP_WAIT0(); } else { CP_WAIT1(); }
        __syncthreads();

        const uint32_t* As = reinterpret_cast<const uint32_t*>(
            dyn + (it & 1) * STAGE_BYTES);
        const uint32_t* Bs = As + A_BYTES / 4;
        const uint32_t* aP = As + (warp_m * 32 + lq) * (AST / 2) + lr;
        const uint32_t* bP = Bs + (warp_n * 64 + lq) * (BST / 2) + lr;

#pragma unroll
        for (int kk = 0; kk < 4; kk++) {      // 4 x k16
            uint32_t au[2][4], bu[8][2];
#pragma unroll
            for (int mi = 0; mi < 2; mi++) {
                const uint32_t* p = aP + mi * 16 * (AST / 2) + kk * 8;
                au[mi][0] = p[0];
                au[mi][1] = p[8 * (AST / 2)];
                au[mi][2] = p[4];
                au[mi][3] = p[8 * (AST / 2) + 4];
            }
#pragma unroll
            for (int nj = 0; nj < 8; nj++) {
                const uint32_t* p = bP + nj * 8 * (BST / 2) + kk * 8;
                bu[nj][0] = p[0];
                bu[nj][1] = p[4];
            }
#pragma unroll
            for (int mi = 0; mi < 2; mi++)
#pragma unroll
                for (int nj = 0; nj < 8; nj++)
                    MMA_F16(acc[mi][nj], au[mi], bu[nj]);
        }
        __syncthreads();
        if (it + 2 < NITER) { load_stage(it + 2, it & 1); CP_COMMIT(); }
    }
    __syncthreads();   // stage buffers dead; smem reused below

    // ======================= epilogue A ====================================
    __half2* Zs2 = reinterpret_cast<__half2*>(dyn);            // [BM][ZST/2]
    const uint32_t pbu = dynb + ZS_BYTES;                      // P chunk bufs

    auto load_pchunk = [&](int kc, int buf) {
        const uint32_t base = pbu + buf * PCH_BYTES;
#pragma unroll
        for (int i = 0; i < 4; i++) {
            const int c = tid + (i << 8);
            if (c < CPAD * 8) {
                const int row = c >> 3, seg = c & 7;
                CP_ASYNC16(base + row * (PST * 2) + seg * 16,
                           g_ph + row * DDIM + kc * 64 + seg * 8);
            }
        }
    };
    load_pchunk(0, 0); CP_COMMIT();

    {
        float rsum[2][2];
#pragma unroll
        for (int mi = 0; mi < 2; mi++) { rsum[mi][0] = 0.f; rsum[mi][1] = 0.f; }

#pragma unroll
        for (int mi = 0; mi < 2; mi++) {
            const int rowA = warp_m * 32 + mi * 16 + lq;
#pragma unroll
            for (int nj = 0; nj < 8; nj++) {
                const int n0 = warp_n * 64 + nj * 8 + 2 * lr;
                float v0 = acc[mi][nj][0] + s_bias[n0];
                float v1 = acc[mi][nj][1] + s_bias[n0 + 1];
                float v2 = acc[mi][nj][2] + s_bias[n0];
                float v3 = acc[mi][nj][3] + s_bias[n0 + 1];
                rsum[mi][0] += v0 * v0 + v1 * v1;
                rsum[mi][1] += v2 * v2 + v3 * v3;
                Zs2[rowA * (ZST / 2) + (n0 >> 1)] = __floats2half2_rn(v0, v1);
                Zs2[(rowA + 8) * (ZST / 2) + (n0 >> 1)] = __floats2half2_rn(v2, v3);
            }
        }
#pragma unroll
        for (int mi = 0; mi < 2; mi++) {
#pragma unroll
            for (int h = 0; h < 2; h++) {
                float s = rsum[mi][h];
                s += __shfl_xor_sync(0xffffffffu, s, 1);
                s += __shfl_xor_sync(0xffffffffu, s, 2);
                if (lr == 0)
                    atomicAdd(&srow[warp_m * 32 + mi * 16 + lq + 8 * h], s);
            }
        }
    }

    // ======================= phase 2: MMA2 =================================
    const int warp_m2 = wid >> 1;   // 0..3 : 16 rows
    const int warp_n2 = wid & 1;    // 0..1 : 56 cols

    float acc2[7][4];
#pragma unroll
    for (int j = 0; j < 7; j++)
#pragma unroll
        for (int r = 0; r < 4; r++) acc2[j][r] = 0.0f;

    const uint32_t* Zs32 = reinterpret_cast<const uint32_t*>(dyn);
    const uint32_t* zP = Zs32 + (warp_m2 * 16 + lq) * (ZST / 2) + lr;

    for (int kc = 0; kc < 4; kc++) {          // 4 chunks of k64
        if (kc + 1 < 4) { load_pchunk(kc + 1, (kc + 1) & 1); CP_COMMIT(); }
        if (kc + 1 < 4) { CP_WAIT1(); } else { CP_WAIT0(); }
        __syncthreads();

        const uint32_t* Ps = reinterpret_cast<const uint32_t*>(
            dyn + ZS_BYTES + (kc & 1) * PCH_BYTES);
        const uint32_t* pP = Ps + (warp_n2 * 56 + lq) * (PST / 2) + lr;

#pragma unroll
        for (int kk = 0; kk < 4; kk++) {
            uint32_t au[4], bu[7][2];
            const uint32_t* zp = zP + kc * 32 + kk * 8;
            au[0] = zp[0];
            au[1] = zp[8 * (ZST / 2)];
            au[2] = zp[4];
            au[3] = zp[8 * (ZST / 2) + 4];
#pragma unroll
            for (int nj = 0; nj < 7; nj++) {
                const uint32_t* p = pP + nj * 8 * (PST / 2) + kk * 8;
                bu[nj][0] = p[0];
                bu[nj][1] = p[4];
            }
#pragma unroll
            for (int nj = 0; nj < 7; nj++)
                MMA_F16(acc2[nj], au, bu[nj]);
        }
        __syncthreads();
    }

    // ======================= epilogue B ====================================
    const float inv = 1.0f / (float)DDIM;
    const int rowA = warp_m2 * 16 + lq;
    const int rowB = rowA + 8;
    const float rsA = srow[rowA];
    const float rsB = srow[rowB];
#pragma unroll
    for (int nj = 0; nj < 7; nj++) {
        const int c0 = warp_n2 * 56 + nj * 8 + 2 * lr;
        const float pn0 = s_pn[c0];
        const float pn1 = s_pn[c0 + 1];
        if (c0 < CNUM)
            out[(size_t)(mBase + rowA) * CNUM + c0] =
                (2.0f * acc2[nj][0] - rsA - pn0) * inv;
        if (c0 + 1 < CNUM)
            out[(size_t)(mBase + rowA) * CNUM + c0 + 1] =
                (2.0f * acc2[nj][1] - rsA - pn1) * inv;
        if (c0 < CNUM)
            out[(size_t)(mBase + rowB) * CNUM + c0] =
                (2.0f * acc2[nj][2] - rsB - pn0) * inv;
        if (c0 + 1 < CNUM)
            out[(size_t)(mBase + rowB) * CNUM + c0 + 1] =
                (2.0f * acc2[nj][3] - rsB - pn1) * inv;
    }
}

// ---------------------------------------------------------------------------
extern "C" void kernel_launch(void* const* d_in, const int* in_sizes, int n_in,
                              void* d_out, int out_size)
{
    const float* x  = (const float*)d_in[0];
    const float* W  = (const float*)d_in[1];
    const float* b  = (const float*)d_in[2];
    const float* P  = (const float*)d_in[3];
    float* out = (float*)d_out;

    cudaFuncSetAttribute(fused_kernel,
                         cudaFuncAttributeMaxDynamicSharedMemorySize, DYN_BYTES);

    prep_kernel<<<PREP_GRID, 256>>>(x, W, P);
    fused_kernel<<<Bsz / BM, NT, DYN_BYTES>>>(b, out);
}

// round 8
// speedup vs baseline: 1.7273x; 1.1458x over previous
#include <cuda_runtime.h>
#include <cuda_fp16.h>
#include <cstdint>

// Problem: B=16384, IN_DIM=1024, D=256, C=100
#define Bsz    16384
#define KDIM   1024
#define DDIM   256
#define CNUM   100
#define CPAD   112

#define BM 128
#define BK 64
#define NITER (KDIM / BK)     // 16
#define NT 512

// fp16-element strides; (stride/2) % 32 == 4 -> conflict-free b32 frag LDS
#define AST 72
#define BST 72
#define ZST 264
#define PST 72

#define A_SLOT_BYTES (BM * AST * 2)       // 18432, 2 slots
#define B_SLOT_BYTES (256 * BST * 2)      // 36864, 3 slots
#define B_OFF (2 * A_SLOT_BYTES)          // 36864
#define DYN_BYTES (B_OFF + 3 * B_SLOT_BYTES)   // 147456

#define ZS_BYTES (BM * ZST * 2)           // 67584 (reuses mainloop smem)
#define PCH_BYTES (CPAD * PST * 2)        // 16128

// Pre-converted fp16 operands (device globals: allocation-free)
__device__ __half g_wt[(size_t)DDIM * KDIM];  // W^T, [n][k]
__device__ __half g_ph[CPAD * DDIM];          // P padded, [c][k]
__device__ float  g_pn[CPAD];                 // |P_c|^2

// ---------------------------------------------------------------------------
__device__ __forceinline__ uint32_t smem_u32(const void* p) {
    uint32_t a;
    asm("{ .reg .u64 t; cvta.to.shared.u64 t, %1; cvt.u32.u64 %0, t; }"
        : "=r"(a) : "l"(p));
    return a;
}

#define CP_ASYNC16(dst, src) \
    asm volatile("cp.async.cg.shared.global [%0], [%1], 16;" \
                 :: "r"(dst), "l"(src) : "memory")
#define CP_COMMIT() asm volatile("cp.async.commit_group;" ::: "memory")
#define CP_WAIT1()  asm volatile("cp.async.wait_group 1;" ::: "memory")
#define CP_WAIT0()  asm volatile("cp.async.wait_group 0;" ::: "memory")

#define MMA_F16(d, a, b) \
    asm volatile("mma.sync.aligned.m16n8k16.row.col.f32.f16.f16.f32 " \
        "{%0,%1,%2,%3}, {%4,%5,%6,%7}, {%8,%9}, {%0,%1,%2,%3};" \
        : "+f"((d)[0]), "+f"((d)[1]), "+f"((d)[2]), "+f"((d)[3]) \
        : "r"((a)[0]), "r"((a)[1]), "r"((a)[2]), "r"((a)[3]), \
          "r"((b)[0]), "r"((b)[1]))

// ---------------------------------------------------------------------------
// Pre-pass (small): W transpose->fp16, P pad->fp16 + |P|^2.
// ---------------------------------------------------------------------------
#define WBLKS 256
#define PBLKS 14
#define PREP_GRID (WBLKS + PBLKS)

__global__ void __launch_bounds__(256)
prep_kernel(const float* __restrict__ W,
            const float* __restrict__ P)
{
    const int b   = blockIdx.x;
    const int tid = threadIdx.x;

    if (b < WBLKS) {
        __shared__ float t[32][33];
        const int bx = (b & 7) * 32;    // n
        const int by = (b >> 3) * 32;   // k
        const int tx = tid & 31, ty = tid >> 5;
#pragma unroll
        for (int j = 0; j < 32; j += 8)
            t[ty + j][tx] = W[(size_t)(by + ty + j) * DDIM + bx + tx];
        __syncthreads();
#pragma unroll
        for (int j = 0; j < 32; j += 8)
            g_wt[(size_t)(bx + ty + j) * KDIM + by + tx] =
                __float2half_rn(t[tx][ty + j]);
    } else {
        const int c    = (b - WBLKS) * 8 + (tid >> 5);
        const int lane = tid & 31;
        float4 v0 = make_float4(0.f, 0.f, 0.f, 0.f), v1 = v0;
        if (c < CNUM) {
            const float4* p4 = reinterpret_cast<const float4*>(P + (size_t)c * DDIM);
            v0 = p4[lane];
            v1 = p4[lane + 32];
        }
        __half2 h0[2] = { __floats2half2_rn(v0.x, v0.y), __floats2half2_rn(v0.z, v0.w) };
        __half2 h1[2] = { __floats2half2_rn(v1.x, v1.y), __floats2half2_rn(v1.z, v1.w) };
        if (c < CPAD) {
            *reinterpret_cast<uint2*>(&g_ph[c * DDIM + lane * 4])       = *reinterpret_cast<uint2*>(h0);
            *reinterpret_cast<uint2*>(&g_ph[c * DDIM + 128 + lane * 4]) = *reinterpret_cast<uint2*>(h1);
        }
        float s = v0.x * v0.x + v0.y * v0.y + v0.z * v0.z + v0.w * v0.w
                + v1.x * v1.x + v1.y * v1.y + v1.z * v1.z + v1.w * v1.w;
#pragma unroll
        for (int o = 16; o > 0; o >>= 1) s += __shfl_xor_sync(0xffffffffu, s, o);
        if (lane == 0 && c < CPAD) g_pn[c] = s;
    }
}

// ---------------------------------------------------------------------------
// Fused kernel: 512 thr / 16 warps, grid 128 (one wave, 1 CTA/SM).
// A path: LDG x fp32 (2 iters ahead) -> cvt -> STS fp16 (double-buffered).
// B path: cp.async from g_wt fp16, 3 stages.
// ---------------------------------------------------------------------------
__global__ void __launch_bounds__(NT, 1)
fused_kernel(const float* __restrict__ x,
             const float* __restrict__ bias,
             float* __restrict__ out)
{
    extern __shared__ __align__(16) unsigned char dyn[];
    __shared__ float s_bias[DDIM];
    __shared__ float srow[BM];
    __shared__ float s_pn[CPAD];

    const int tid  = threadIdx.x;
    const int wid  = tid >> 5;
    const int lane = tid & 31;
    const int lq = lane >> 2;
    const int lr = lane & 3;
    const int mBase = blockIdx.x * BM;

    const int warp_m = wid & 1;    // 0..1 : 64 rows
    const int warp_n = wid >> 1;   // 0..7 : 32 cols

    if (tid < DDIM) s_bias[tid] = bias[tid];
    if (tid < BM)   srow[tid] = 0.0f;
    if (tid < CPAD) s_pn[tid] = g_pn[tid];

    const uint32_t dynb = smem_u32(dyn);

    // ---- A path: row = tid>>2, quarter = tid&3 ----
    const int arow = tid >> 2;
    const int aq   = tid & 3;
    const float4* xsrc = reinterpret_cast<const float4*>(
        x + (size_t)(mBase + arow) * KDIM + aq * 16);

    uint32_t hbuf[8];
    auto ldgA = [&](int kIter) {
        const float4* s = xsrc + kIter * (BK / 4);
#pragma unroll
        for (int j = 0; j < 4; j++) {
            float4 v = s[j];
            __half2 h0 = __floats2half2_rn(v.x, v.y);
            __half2 h1 = __floats2half2_rn(v.z, v.w);
            hbuf[2 * j]     = *reinterpret_cast<uint32_t*>(&h0);
            hbuf[2 * j + 1] = *reinterpret_cast<uint32_t*>(&h1);
        }
    };
    auto stsA = [&](int slot) {
        uint32_t* d = reinterpret_cast<uint32_t*>(dyn + slot * A_SLOT_BYTES)
                      + arow * (AST / 2) + aq * 8;
#pragma unroll
        for (int j = 0; j < 8; j++) d[j] = hbuf[j];
    };

    auto loadB = [&](int kIter, int slot) {
        const int k0 = kIter * BK;
        const uint32_t bB = dynb + B_OFF + slot * B_SLOT_BYTES;
#pragma unroll
        for (int i = 0; i < 4; i++) {
            const int c = tid + (i << 9);
            const int row = c >> 3, seg = c & 7;
            CP_ASYNC16(bB + row * (BST * 2) + seg * 16,
                       g_wt + (size_t)row * KDIM + k0 + seg * 8);
        }
    };

    // prologue
    ldgA(0); stsA(0); ldgA(1);
    loadB(0, 0); CP_COMMIT();
    loadB(1, 1); CP_COMMIT();

    float acc[4][4][4];
#pragma unroll
    for (int i = 0; i < 4; i++)
#pragma unroll
        for (int j = 0; j < 4; j++)
#pragma unroll
            for (int r = 0; r < 4; r++) acc[i][j][r] = 0.0f;

    for (int it = 0; it < NITER; ++it) {
        if (it == NITER - 1) { CP_WAIT0(); } else { CP_WAIT1(); }
        __syncthreads();

        if (it + 2 < NITER) { loadB(it + 2, (it + 2) % 3); CP_COMMIT(); }
        if (it + 1 < NITER) stsA((it + 1) & 1);
        if (it + 2 < NITER) ldgA(it + 2);

        const uint32_t* As = reinterpret_cast<const uint32_t*>(
            dyn + (it & 1) * A_SLOT_BYTES);
        const uint32_t* Bs = reinterpret_cast<const uint32_t*>(
            dyn + B_OFF + (it % 3) * B_SLOT_BYTES);
        const uint32_t* aP = As + (warp_m * 64 + lq) * (AST / 2) + lr;
        const uint32_t* bP = Bs + (warp_n * 32 + lq) * (BST / 2) + lr;

#pragma unroll
        for (int kk = 0; kk < 4; kk++) {
            uint32_t au[4][4], bu[4][2];
#pragma unroll
            for (int mi = 0; mi < 4; mi++) {
                const uint32_t* p = aP + mi * 16 * (AST / 2) + kk * 8;
                au[mi][0] = p[0];
                au[mi][1] = p[8 * (AST / 2)];
                au[mi][2] = p[4];
                au[mi][3] = p[8 * (AST / 2) + 4];
            }
#pragma unroll
            for (int nj = 0; nj < 4; nj++) {
                const uint32_t* p = bP + nj * 8 * (BST / 2) + kk * 8;
                bu[nj][0] = p[0];
                bu[nj][1] = p[4];
            }
#pragma unroll
            for (int mi = 0; mi < 4; mi++)
#pragma unroll
                for (int nj = 0; nj < 4; nj++)
                    MMA_F16(acc[mi][nj], au[mi], bu[nj]);
        }
    }
    __syncthreads();

    // ======================= epilogue A ====================================
    __half2* Zs2 = reinterpret_cast<__half2*>(dyn);
    const uint32_t pbu = dynb + ZS_BYTES;

    auto load_pchunk = [&](int kc, int buf) {
        const uint32_t base = pbu + buf * PCH_BYTES;
#pragma unroll
        for (int i = 0; i < 2; i++) {
            const int c = tid + (i << 9);
            if (c < CPAD * 8) {
                const int row = c >> 3, seg = c & 7;
                CP_ASYNC16(base + row * (PST * 2) + seg * 16,
                           g_ph + row * DDIM + kc * 64 + seg * 8);
            }
        }
    };
    load_pchunk(0, 0); CP_COMMIT();

    {
        float rsum[4][2];
#pragma unroll
        for (int mi = 0; mi < 4; mi++) { rsum[mi][0] = 0.f; rsum[mi][1] = 0.f; }

#pragma unroll
        for (int mi = 0; mi < 4; mi++) {
            const int rowA = warp_m * 64 + mi * 16 + lq;
#pragma unroll
            for (int nj = 0; nj < 4; nj++) {
                const int n0 = warp_n * 32 + nj * 8 + 2 * lr;
                float v0 = acc[mi][nj][0] + s_bias[n0];
                float v1 = acc[mi][nj][1] + s_bias[n0 + 1];
                float v2 = acc[mi][nj][2] + s_bias[n0];
                float v3 = acc[mi][nj][3] + s_bias[n0 + 1];
                rsum[mi][0] += v0 * v0 + v1 * v1;
                rsum[mi][1] += v2 * v2 + v3 * v3;
                Zs2[rowA * (ZST / 2) + (n0 >> 1)] = __floats2half2_rn(v0, v1);
                Zs2[(rowA + 8) * (ZST / 2) + (n0 >> 1)] = __floats2half2_rn(v2, v3);
            }
        }
#pragma unroll
        for (int mi = 0; mi < 4; mi++) {
#pragma unroll
            for (int h = 0; h < 2; h++) {
                float s = rsum[mi][h];
                s += __shfl_xor_sync(0xffffffffu, s, 1);
                s += __shfl_xor_sync(0xffffffffu, s, 2);
                if (lr == 0)
                    atomicAdd(&srow[warp_m * 64 + mi * 16 + lq + 8 * h], s);
            }
        }
    }

    // ======================= phase 2: MMA2 =================================
    const int warp_m2 = wid >> 1;
    const int warp_n2 = wid & 1;

    float acc2[7][4];
#pragma unroll
    for (int j = 0; j < 7; j++)
#pragma unroll
        for (int r = 0; r < 4; r++) acc2[j][r] = 0.0f;

    const uint32_t* Zs32 = reinterpret_cast<const uint32_t*>(dyn);
    const uint32_t* zP = Zs32 + (warp_m2 * 16 + lq) * (ZST / 2) + lr;

    for (int kc = 0; kc < 4; kc++) {
        if (kc + 1 < 4) { load_pchunk(kc + 1, (kc + 1) & 1); CP_COMMIT(); }
        if (kc + 1 < 4) { CP_WAIT1(); } else { CP_WAIT0(); }
        __syncthreads();

        const uint32_t* Ps = reinterpret_cast<const uint32_t*>(
            dyn + ZS_BYTES + (kc & 1) * PCH_BYTES);
        const uint32_t* pP = Ps + (warp_n2 * 56 + lq) * (PST / 2) + lr;

#pragma unroll
        for (int kk = 0; kk < 4; kk++) {
            uint32_t au[4], bu[7][2];
            const uint32_t* zp = zP + kc * 32 + kk * 8;
            au[0] = zp[0];
            au[1] = zp[8 * (ZST / 2)];
            au[2] = zp[4];
            au[3] = zp[8 * (ZST / 2) + 4];
#pragma unroll
            for (int nj = 0; nj < 7; nj++) {
                const uint32_t* p = pP + nj * 8 * (PST / 2) + kk * 8;
                bu[nj][0] = p[0];
                bu[nj][1] = p[4];
            }
#pragma unroll
            for (int nj = 0; nj < 7; nj++)
                MMA_F16(acc2[nj], au, bu[nj]);
        }
        __syncthreads();
    }

    // ======================= epilogue B ====================================
    const float inv = 1.0f / (float)DDIM;
    const int rowA = warp_m2 * 16 + lq;
    const int rowB = rowA + 8;
    const float rsA = srow[rowA];
    const float rsB = srow[rowB];
#pragma unroll
    for (int nj = 0; nj < 7; nj++) {
        const int c0 = warp_n2 * 56 + nj * 8 + 2 * lr;
        const float pn0 = s_pn[c0];
        const float pn1 = s_pn[c0 + 1];
        if (c0 < CNUM)
            out[(size_t)(mBase + rowA) * CNUM + c0] =
                (2.0f * acc2[nj][0] - rsA - pn0) * inv;
        if (c0 + 1 < CNUM)
            out[(size_t)(mBase + rowA) * CNUM + c0 + 1] =
                (2.0f * acc2[nj][1] - rsA - pn1) * inv;
        if (c0 < CNUM)
            out[(size_t)(mBase + rowB) * CNUM + c0] =
                (2.0f * acc2[nj][2] - rsB - pn0) * inv;
        if (c0 + 1 < CNUM)
            out[(size_t)(mBase + rowB) * CNUM + c0 + 1] =
                (2.0f * acc2[nj][3] - rsB - pn1) * inv;
    }
}

// ---------------------------------------------------------------------------
extern "C" void kernel_launch(void* const* d_in, const int* in_sizes, int n_in,
                              void* d_out, int out_size)
{
    const float* x  = (const float*)d_in[0];
    const float* W  = (const float*)d_in[1];
    const float* b  = (const float*)d_in[2];
    const float* P  = (const float*)d_in[3];
    float* out = (float*)d_out;

    cudaFuncSetAttribute(fused_kernel,
                         cudaFuncAttributeMaxDynamicSharedMemorySize, DYN_BYTES);

    prep_kernel<<<PREP_GRID, 256>>>(W, P);
    fused_kernel<<<Bsz / BM, NT, DYN_BYTES>>>(x, b, out);
}